// round 11
// baseline (speedup 1.0000x reference)
#include <cuda_runtime.h>

// Problem constants (fixed by the dataset)
#define BB   256
#define NN   32
#define WW   1920
#define HH   1080
#define ROWS (BB * NN)                 // 8192
#define NX4  (ROWS * (WW / 4))         // 3,932,160 float4 in pred_x
#define NY4  (ROWS * (HH / 4))         // 2,211,840 float4 in pred_y
#define NSLOTS 32
#define GRIDX  888                     // 148 SMs * 6 blocks

// Scratch (__device__ globals; zero at module load, reset by last block each run)
__device__ float        g_accs[NSLOTS];
__device__ float        g_count;
__device__ int          g_nmasked;
__device__ int          g_masked[ROWS];
__device__ unsigned int g_done;

__inline__ __device__ float warp_sum(float v) {
    #pragma unroll
    for (int o = 16; o > 0; o >>= 1)
        v += __shfl_xor_sync(0xffffffffu, v, o);
    return v;
}

// sum of clamp(log(1-p), -100) over a float4
__inline__ __device__ float l1term(float4 v) {
    return fmaxf(__logf(1.0f - v.x), -100.0f)
         + fmaxf(__logf(1.0f - v.y), -100.0f)
         + fmaxf(__logf(1.0f - v.z), -100.0f)
         + fmaxf(__logf(1.0f - v.w), -100.0f);
}

__global__ void __launch_bounds__(256)
hbdl_kernel(const float* __restrict__ px,
            const float* __restrict__ py,
            const long long* __restrict__ tgt,
            float* __restrict__ out) {
    const int tid = threadIdx.x;
    const int bid = blockIdx.x;
    const size_t st = (size_t)GRIDX * 256;   // grid stride in float4 units

    float contrib = 0.0f;

    // ---- gather terms + mask/count/masked-list: blocks 0..31, one row/thread ----
    if (bid < ROWS / 256) {
        int r = bid * 256 + tid;
        longlong2 t2 = ((const longlong2*)tgt)[r];
        int tx = min(max((int)t2.x, 0), WW - 1);
        int ty = min(max((int)t2.y, 0), HH - 1);
        bool valid = !((tx == 0) && (ty == 0));
        if (valid) {
            float p = __ldg(px + (size_t)r * WW + tx);
            float q = __ldg(py + (size_t)r * HH + ty);
            contrib += (fmaxf(__logf(1.0f - p), -100.0f) - fmaxf(__logf(p), -100.0f)) * (1.0f / WW)
                     + (fmaxf(__logf(1.0f - q), -100.0f) - fmaxf(__logf(q), -100.0f)) * (1.0f / HH);
        } else {
            int slot = atomicAdd(&g_nmasked, 1);
            g_masked[slot] = r;
        }
        unsigned bal = __ballot_sync(0xffffffffu, valid);
        if ((tid & 31) == 0) atomicAdd(&g_count, (float)__popc(bal));
    }

    // ---- flat unmasked stream over pred_x: -sum(l1p)/W ----
    {
        const float4* p4 = (const float4*)px;
        size_t i = (size_t)bid * 256 + tid;
        float s = 0.0f;
        for (; i + 3 * st < NX4; i += 4 * st) {
            float4 a = p4[i], b = p4[i + st], c = p4[i + 2 * st], d = p4[i + 3 * st];
            s += l1term(a) + l1term(b) + l1term(c) + l1term(d);
        }
        for (; i < NX4; i += st) s += l1term(p4[i]);
        contrib -= s * (1.0f / WW);
    }

    // ---- flat unmasked stream over pred_y: -sum(l1p)/H ----
    {
        const float4* p4 = (const float4*)py;
        size_t i = (size_t)bid * 256 + tid;
        float s = 0.0f;
        for (; i + 3 * st < NY4; i += 4 * st) {
            float4 a = p4[i], b = p4[i + st], c = p4[i + 2 * st], d = p4[i + 3 * st];
            s += l1term(a) + l1term(b) + l1term(c) + l1term(d);
        }
        for (; i < NY4; i += st) s += l1term(p4[i]);
        contrib -= s * (1.0f / HH);
    }

    // ---- block reduce -> striped atomic ----
    __shared__ float sh[8];
    int lane = tid & 31;
    int wid  = tid >> 5;
    float bsum = warp_sum(contrib);
    if (lane == 0) sh[wid] = bsum;
    __syncthreads();
    if (tid == 0) {
        float t = 0.0f;
        #pragma unroll
        for (int w = 0; w < 8; w++) t += sh[w];
        atomicAdd(&g_accs[bid & (NSLOTS - 1)], t);
    }

    // ---- ticket: last block finalizes ----
    __shared__ bool isLast;
    if (tid == 0) {
        __threadfence();
        isLast = (atomicAdd(&g_done, 1u) == (unsigned)(GRIDX - 1));
    }
    __syncthreads();
    if (!isLast) return;

    // Correction: the stream included masked rows; add their sums back.
    // (Expected empty list; correct for any input.)
    int nm = atomicAdd(&g_nmasked, 0);
    float corr = 0.0f;
    for (int j = 0; j < nm; j++) {
        int r = __ldcg(&g_masked[j]);
        const float4* pr = (const float4*)(px + (size_t)r * WW);
        float sx = 0.0f;
        for (int i = tid; i < WW / 4; i += 256) sx += l1term(pr[i]);
        corr += sx * (1.0f / WW);
        const float4* qr = (const float4*)(py + (size_t)r * HH);
        float sy = 0.0f;
        for (int i = tid; i < HH / 4; i += 256) sy += l1term(qr[i]);
        corr += sy * (1.0f / HH);
    }
    // reduce corr across the block
    float cw = warp_sum(corr);
    if (lane == 0) sh[wid] = cw;
    __syncthreads();
    if (tid == 0) {
        float acc = 0.0f;
        #pragma unroll
        for (int w = 0; w < 8; w++) acc += sh[w];
        #pragma unroll
        for (int i = 0; i < NSLOTS; i++) acc += atomicAdd(&g_accs[i], 0.0f);
        float cnt = atomicAdd(&g_count, 0.0f);
        out[0] = acc / fmaxf(cnt, 1.0f);
        // reset scratch for the next (graph) replay
        #pragma unroll
        for (int i = 0; i < NSLOTS; i++) g_accs[i] = 0.0f;
        g_count   = 0.0f;
        g_nmasked = 0;
        g_done    = 0u;
    }
}

extern "C" void kernel_launch(void* const* d_in, const int* in_sizes, int n_in,
                              void* d_out, int out_size) {
    const float*     px  = (const float*)d_in[0];       // [256,32,1920] f32
    const float*     py  = (const float*)d_in[1];       // [256,32,1080] f32
    const long long* tgt = (const long long*)d_in[2];   // [256,32,2] i64
    float* out = (float*)d_out;

    hbdl_kernel<<<GRIDX, 256>>>(px, py, tgt, out);
}

// round 12
// speedup vs baseline: 391.6862x; 391.6862x over previous
#include <cuda_runtime.h>

// Problem constants (fixed by the dataset)
#define BB   256
#define NN   32
#define WW   1920
#define HH   1080
#define ROWS   (BB * NN)        // 8192
#define NWARPS (2 * ROWS)       // 16384 warps: [0,ROWS)=x-rows, [ROWS,2*ROWS)=y-rows
#define WPB    8                // warps per block
#define GRIDX  (NWARPS / WPB)   // 2048 blocks
#define NSLOTS 32

// Scratch (__device__ globals; zero at load, reset by last block every launch
// so graph replays are deterministic). Pattern identical to R5 (proven under replay).
__device__ float        g_accs[NSLOTS];
__device__ float        g_counts[NSLOTS];
__device__ unsigned int g_done;

__inline__ __device__ float warp_sum(float v) {
    #pragma unroll
    for (int o = 16; o > 0; o >>= 1)
        v += __shfl_xor_sync(0xffffffffu, v, o);
    return v;
}

// sum of clamp(log(1-p), -100) over a float4
__inline__ __device__ float l1term(float4 v) {
    return fmaxf(__logf(1.0f - v.x), -100.0f)
         + fmaxf(__logf(1.0f - v.y), -100.0f)
         + fmaxf(__logf(1.0f - v.z), -100.0f)
         + fmaxf(__logf(1.0f - v.w), -100.0f);
}

__global__ void __launch_bounds__(256)
hbdl_kernel(const float* __restrict__ px,
            const float* __restrict__ py,
            const long long* __restrict__ tgt,
            float* __restrict__ out) {
    const int tid  = threadIdx.x;
    const int lane = tid & 31;
    const int wid  = tid >> 5;
    const int gw   = blockIdx.x * WPB + wid;    // global warp id, [0, 16384)
    const bool is_x = (gw < ROWS);
    const int r    = is_x ? gw : gw - ROWS;

    // --- mask + target for this warp's row (16B, L2-hot; lane 0 loads, broadcast) ---
    long long t0 = 0, t1 = 0;
    if (lane == 0) {
        longlong2 t2 = ((const longlong2*)tgt)[r];
        t0 = t2.x; t1 = t2.y;
    }
    int tx = __shfl_sync(0xffffffffu, (int)t0, 0);
    int ty = __shfl_sync(0xffffffffu, (int)t1, 0);
    tx = min(max(tx, 0), WW - 1);
    ty = min(max(ty, 0), HH - 1);
    const bool valid = !((tx == 0) && (ty == 0));

    float contrib = 0.0f;   // lane-0-of-warp value after warp reduce

    if (valid) {
        float s = 0.0f;           // sum of clamped log(1-p) over this warp's row
        int   t_idx;
        float inv_l;
        const float* rowp;

        if (is_x) {
            rowp  = px + (size_t)r * WW;
            inv_l = 1.0f / (float)WW;
            t_idx = tx;
            const float4* p4 = (const float4*)rowp;   // 480 float4 = 15 iters/lane
            #pragma unroll 5
            for (int k = 0; k < 15; k++)
                s += l1term(p4[k * 32 + lane]);
        } else {
            rowp  = py + (size_t)r * HH;
            inv_l = 1.0f / (float)HH;
            t_idx = ty;
            const float4* p4 = (const float4*)rowp;   // 270 float4 = 8 iters + 14-lane tail
            #pragma unroll
            for (int k = 0; k < 8; k++)
                s += l1term(p4[k * 32 + lane]);
            if (lane < 14)
                s += l1term(p4[256 + lane]);
        }

        float ws = warp_sum(s);
        if (lane == 0) {
            // row loss contribution: (-lp[t] - (sum_l1p - l1p[t])) / L
            float p   = rowp[t_idx];
            float lp  = fmaxf(__logf(p),        -100.0f);
            float l1p = fmaxf(__logf(1.0f - p), -100.0f);
            contrib = (l1p - lp - ws) * inv_l;
            if (is_x)   // count each valid (b,n) once (x-warps only)
                atomicAdd(&g_counts[blockIdx.x & (NSLOTS - 1)], 1.0f);
        }
    }

    // --- block reduce (8 warps) -> one striped atomic per block ---
    __shared__ float sh[WPB];
    if (lane == 0) sh[wid] = contrib;
    __syncthreads();
    if (tid == 0) {
        float t = 0.0f;
        #pragma unroll
        for (int w = 0; w < WPB; w++) t += sh[w];
        atomicAdd(&g_accs[blockIdx.x & (NSLOTS - 1)], t);
    }

    // --- ticket: last block finalizes + resets scratch ---
    __shared__ bool isLast;
    if (tid == 0) {
        __threadfence();
        isLast = (atomicAdd(&g_done, 1u) == (unsigned)(GRIDX - 1));
    }
    __syncthreads();
    if (isLast && tid < NSLOTS) {
        volatile float* va = g_accs;
        volatile float* vc = g_counts;
        float a = va[tid];
        float c = vc[tid];
        a = warp_sum(a);
        c = warp_sum(c);
        if (tid == 0) {
            out[0] = a / fmaxf(c, 1.0f);
            g_done = 0u;
        }
        g_accs[tid]   = 0.0f;
        g_counts[tid] = 0.0f;
    }
}

extern "C" void kernel_launch(void* const* d_in, const int* in_sizes, int n_in,
                              void* d_out, int out_size) {
    const float*     px  = (const float*)d_in[0];       // [256,32,1920] f32
    const float*     py  = (const float*)d_in[1];       // [256,32,1080] f32
    const long long* tgt = (const long long*)d_in[2];   // [256,32,2] i64
    float* out = (float*)d_out;

    hbdl_kernel<<<GRIDX, 256>>>(px, py, tgt, out);
}